// round 15
// baseline (speedup 1.0000x reference)
#include <cuda_runtime.h>
#include <cstdint>

#define NE    8192
#define DIM   128
#define PMAX  5
#define NNODE 512
#define TOTAL (NNODE * NNODE)

#define CTAS         128
#define THREADS      1024
#define EDGES_CTA    (NE / CTAS)               // 64 (warp -> 2 edges)
#define PAIRS_CTA    (TOTAL / CTAS)            // 2048
#define TBL_BYTES    (PMAX * NE * 4)           // 163840, layout [p][e]
#define CHUNK_BYTES  (NE * 4)                  // 32768 (one p slice)
#define PATH_BYTES   (PAIRS_CTA * PMAX * 4)    // 40960
#define SMEM_BYTES   (TBL_BYTES + PATH_BYTES)  // 204800

// Precomputed dot products, layout [p][e].
__device__ float g_dots[PMAX * NE];
// Monotone counters (never reset -> graph-replay safe).
__device__ unsigned int g_done = 0;   // +CTAS per replay
__device__ unsigned int g_gen  = 0;   // +CTAS per replay

__device__ __forceinline__ uint32_t smem_u32(const void* p) {
    return (uint32_t)__cvta_generic_to_shared(p);
}

__device__ __forceinline__ void cp16(uint32_t dst, const void* src) {
    asm volatile("cp.async.cg.shared.global [%0], [%1], 16;"
                 :: "r"(dst), "l"(src) : "memory");
}

// ---------------------------------------------------------------------------
// Fused kernel: 128 CTAs x 1024 threads, single wave (spin-barrier safe).
//   1. paths cp.async issued at entry (arrives during dot phase)
//   2. dot phase: CTA b computes edges [64b, 64b+64), warp -> 2 edges
//   3. monotone-counter grid barrier (one atomic + one spinner per CTA)
//   4. distributed cp.async table fill (5 p-chunks) + pipelined LDS gather
// ---------------------------------------------------------------------------
__global__ __launch_bounds__(THREADS, 1) void fused_kernel(
        const float* __restrict__ emb, const float* __restrict__ ev,
        const int*   __restrict__ paths, float* __restrict__ out) {
    extern __shared__ __align__(16) char smem[];
    float* s_dots  = (float*)smem;                 // 163840 B, [p][e]
    int*   s_paths = (int*)(smem + TBL_BYTES);     // 40960 B

    const int tid  = threadIdx.x;
    const int lane = tid & 31;
    const int w    = tid >> 5;                     // 0..31

    // ---- group 0: paths slice (2560 x 16B ops across 1024 threads) ----
    {
        const char* src = (const char*)paths + blockIdx.x * PATH_BYTES;
        uint32_t    dst = smem_u32(s_paths);
        cp16(dst + tid * 16,          src + tid * 16);
        cp16(dst + (tid + 1024) * 16, src + (tid + 1024) * 16);
        if (tid < 512)
            cp16(dst + (tid + 2048) * 16, src + (tid + 2048) * 16);
        asm volatile("cp.async.commit_group;" ::: "memory");
    }

    // ---- dot phase: edges e0, e0+1 for this warp ----
    {
        const int e0 = blockIdx.x * EDGES_CTA + w * 2;

        float4 a0 = __ldg(((const float4*)emb) + (e0    ) * (DIM / 4) + lane);
        float4 a1 = __ldg(((const float4*)emb) + (e0 + 1) * (DIM / 4) + lane);

        float4 evr[PMAX];
#pragma unroll
        for (int p = 0; p < PMAX; ++p)
            evr[p] = __ldg(((const float4*)ev) + p * (DIM / 4) + lane);

        float pa[PMAX], pb[PMAX];
#pragma unroll
        for (int p = 0; p < PMAX; ++p) {
            pa[p] = a0.x * evr[p].x + a0.y * evr[p].y + a0.z * evr[p].z + a0.w * evr[p].w;
            pb[p] = a1.x * evr[p].x + a1.y * evr[p].y + a1.z * evr[p].z + a1.w * evr[p].w;
        }
#pragma unroll
        for (int off = 16; off > 0; off >>= 1) {
#pragma unroll
            for (int p = 0; p < PMAX; ++p) {
                pa[p] += __shfl_xor_sync(0xffffffffu, pa[p], off);
                pb[p] += __shfl_xor_sync(0xffffffffu, pb[p], off);
            }
        }
        if (lane == 0) {
#pragma unroll
            for (int p = 0; p < PMAX; ++p) {
                g_dots[p * NE + e0]     = pa[p];
                g_dots[p * NE + e0 + 1] = pb[p];
            }
            __threadfence();            // flush this warp's dot STGs GPU-wide
        }
    }
    __syncthreads();
    if (tid == 0)
        atomicAdd(&g_done, 1u);         // this CTA's dots are visible

    // ---- indices while other CTAs finish their dots ----
    asm volatile("cp.async.wait_group 0;" ::: "memory");   // paths arrived
    __syncthreads();
    int e0i[PMAX], e1i[PMAX];
#pragma unroll
    for (int p = 0; p < PMAX; ++p) e0i[p] = s_paths[5 * tid + p];
#pragma unroll
    for (int p = 0; p < PMAX; ++p) e1i[p] = s_paths[5 * (tid + 1024) + p];

    int c0 = 0, c1 = 0;
#pragma unroll
    for (int p = 0; p < PMAX; ++p) { if (e0i[p] >= 0) ++c0; if (e1i[p] >= 0) ++c1; }

    // ---- grid barrier: wait until all CTAs published their dots ----
    if (tid == 0) {
        unsigned int t = atomicAdd(&g_gen, 1u);
        unsigned int target = (t / CTAS + 1u) * CTAS;
        volatile unsigned int* vd = &g_done;
        while (*vd < target) { }
        __threadfence();                                // acquire
    }
    __syncthreads();

    // ---- table fill: 5 groups, one p-chunk each (2 x 16B ops/thread) ----
#pragma unroll
    for (int p = 0; p < PMAX; ++p) {
        const char* src = (const char*)g_dots + p * CHUNK_BYTES;
        uint32_t    dst = smem_u32(s_dots) + p * CHUNK_BYTES;
        cp16(dst + tid * 16,          src + tid * 16);
        cp16(dst + (tid + 1024) * 16, src + (tid + 1024) * 16);
        asm volatile("cp.async.commit_group;" ::: "memory");
    }

    // ---- pipelined gather: consume each p-chunk as it completes ----
    float a0 = 0.f, a1 = 0.f;
#pragma unroll
    for (int p = 0; p < PMAX; ++p) {
        switch (p) {   // wait_group needs an immediate
            case 0: asm volatile("cp.async.wait_group 4;" ::: "memory"); break;
            case 1: asm volatile("cp.async.wait_group 3;" ::: "memory"); break;
            case 2: asm volatile("cp.async.wait_group 2;" ::: "memory"); break;
            case 3: asm volatile("cp.async.wait_group 1;" ::: "memory"); break;
            case 4: asm volatile("cp.async.wait_group 0;" ::: "memory"); break;
        }
        __syncthreads();
        const float* tp = s_dots + p * NE;
        if (e0i[p] >= 0) a0 += tp[e0i[p]];
        if (e1i[p] >= 0) a1 += tp[e1i[p]];
    }

    float* ob = out + blockIdx.x * PAIRS_CTA;
    ob[tid]        = c0 ? a0 / (float)c0 : 0.0f;
    ob[tid + 1024] = c1 ? a1 / (float)c1 : 0.0f;
}

// ---------------------------------------------------------------------------
// Launch
// ---------------------------------------------------------------------------
extern "C" void kernel_launch(void* const* d_in, const int* in_sizes, int n_in,
                              void* d_out, int out_size) {
    const float* emb   = nullptr;
    const int*   paths = nullptr;
    const float* ev    = nullptr;
    for (int i = 0; i < n_in; ++i) {
        if (in_sizes[i] == NE * DIM)                  emb   = (const float*)d_in[i];
        else if (in_sizes[i] == NNODE * NNODE * PMAX) paths = (const int*)d_in[i];
        else if (in_sizes[i] == PMAX * DIM)           ev    = (const float*)d_in[i];
    }
    float* out = (float*)d_out;

    cudaFuncSetAttribute(fused_kernel,
                         cudaFuncAttributeMaxDynamicSharedMemorySize,
                         SMEM_BYTES);
    fused_kernel<<<CTAS, THREADS, SMEM_BYTES>>>(emb, ev, paths, out);
}